// round 7
// baseline (speedup 1.0000x reference)
#include <cuda_runtime.h>
#include <cstdint>
#include <cstddef>

// Problem constants
#define T_STEPS 512
#define BATCH   128
#define N_INP   256
#define N_HID   1024
#define N_OUT   128

#define SPLITK  16                 // K-split for the recurrent GEMM (K=1024 -> 64/slice)
#define KSLICE  (N_HID / SPLITK)   // 64
#define KC      32                 // k per smem chunk
#define KPAIRS  (KC / 2)           // 16 float2 pairs per chunk
#define NCTA    128                // persistent grid size (<= 148 SMs -> co-resident)

// -------- scratch (device globals; no runtime allocation allowed) --------
__device__ float g_xp[(size_t)T_STEPS * BATCH * N_HID];   // input projection (+biases)
__device__ float g_partial[SPLITK * BATCH * N_HID];       // split-K partials (reused by readout)
__device__ float g_state[BATCH * N_HID];                  // hidden state
__device__ unsigned g_count;                              // barrier arrivals (monotonic)
__device__ unsigned g_gen;                                // barrier generation (monotonic)

// -------- packed f32x2 FMA (full-rate fp32 on sm_103a; FFMA-3reg is half rate) --------
__device__ __forceinline__ unsigned long long ffma2(unsigned long long a,
                                                    unsigned long long b,
                                                    unsigned long long c) {
    unsigned long long d;
    asm("fma.rn.f32x2 %0, %1, %2, %3;" : "=l"(d) : "l"(a), "l"(b), "l"(c));
    return d;
}
__device__ __forceinline__ float lo32(unsigned long long v) {
    return __uint_as_float((unsigned)(v & 0xffffffffull));
}
__device__ __forceinline__ float hi32(unsigned long long v) {
    return __uint_as_float((unsigned)(v >> 32));
}

// -------- software grid barrier (CG grid.sync pattern; targets are monotonic) --------
__device__ __forceinline__ void grid_barrier(unsigned target) {
    __syncthreads();
    if (threadIdx.x == 0) {
        __threadfence();                         // release my CTA's prior writes
        unsigned old = atomicAdd(&g_count, 1u);  // morally-strong arrive
        if (old == (unsigned)NCTA * target - 1u) {
            asm volatile("st.release.gpu.u32 [%0], %1;"
                         :: "l"(&g_gen), "r"(target) : "memory");
        } else {
            unsigned v;
            do {
                asm volatile("ld.acquire.gpu.u32 %0, [%1];"
                             : "=r"(v) : "l"(&g_gen) : "memory");
            } while (v < target);
        }
    }
    __syncthreads();   // extends thread0's acquire to the whole CTA
}

// Load a [KC x 128] tile (rows = 128 b/h indices, KC contiguous k) into smem laid
// out as S[kpair][row] = (src[row][k0+2kp], src[row][k0+2kp+1]). Coalesced float4s.
__device__ __forceinline__ void load_tile(float2 (*S)[128],
                                          const float* __restrict__ src,
                                          size_t rowbase, int ld, int k0, int tid) {
#pragma unroll
    for (int r = 0; r < 4; r++) {
        int f   = r * 256 + tid;     // float4 index within tile: 1024 total
        int row = f >> 3;            // 8 float4 per row (KC=32 floats)
        int fq  = f & 7;
        const float4 v = *reinterpret_cast<const float4*>(
            src + (rowbase + (size_t)row) * (size_t)ld + k0 + fq * 4);
        S[2 * fq + 0][row] = make_float2(v.x, v.y);
        S[2 * fq + 1][row] = make_float2(v.z, v.w);
    }
}

// 8x8 per-thread outer product over one KC chunk, f32x2-packed along k.
__device__ __forceinline__ void compute_chunk(const float2 (*Ss)[128],
                                              const float2 (*Ws)[128],
                                              int ty, int tx,
                                              unsigned long long (*acc)[8]) {
#pragma unroll
    for (int kp = 0; kp < KPAIRS; kp++) {
        unsigned long long s[8], w[8];
        const ulonglong2* sp = reinterpret_cast<const ulonglong2*>(&Ss[kp][ty * 8]);
#pragma unroll
        for (int q = 0; q < 4; q++) {
            ulonglong2 v = sp[q];
            s[2 * q + 0] = v.x;
            s[2 * q + 1] = v.y;
        }
#pragma unroll
        for (int j = 0; j < 8; j++) {
            w[j] = *reinterpret_cast<const unsigned long long*>(&Ws[kp][tx + 16 * j]);
        }
#pragma unroll
        for (int i = 0; i < 8; i++) {
#pragma unroll
            for (int j = 0; j < 8; j++) {
                acc[i][j] = ffma2(s[i], w[j], acc[i][j]);
            }
        }
    }
}

// -------- kernels --------

// Zero state + barrier counters (buffers persist across graph replays).
__global__ __launch_bounds__(256, 1) void init_kernel() {
    reinterpret_cast<float4*>(g_state)[blockIdx.x * 256 + threadIdx.x] =
        make_float4(0.f, 0.f, 0.f, 0.f);
    if (blockIdx.x == 0 && threadIdx.x == 0) {
        g_count = 0u;
        g_gen   = 0u;
    }
}

// x_proj[t*B+b][h] = sum_k x[t,b,k] * W_ih[h,k] + b_ih[h] + b_hh[h]
__global__ __launch_bounds__(256, 1) void xproj_kernel(const float* __restrict__ x,
                                                       const float* __restrict__ W_ih,
                                                       const float* __restrict__ b_ih,
                                                       const float* __restrict__ b_hh) {
    __shared__ alignas(16) float2 Ss[KPAIRS][128];
    __shared__ alignas(16) float2 Ws[KPAIRS][128];
    const int tid = threadIdx.x;
    const int tx = tid & 15, ty = tid >> 4;
    const int mtile = blockIdx.x, htile = blockIdx.y;

    unsigned long long acc[8][8];
#pragma unroll
    for (int i = 0; i < 8; i++)
#pragma unroll
        for (int j = 0; j < 8; j++) acc[i][j] = 0ull;

    for (int c = 0; c < N_INP / KC; c++) {
        const int k0 = c * KC;
        load_tile(Ss, x,    (size_t)mtile * 128, N_INP, k0, tid);
        load_tile(Ws, W_ih, (size_t)htile * 128, N_INP, k0, tid);
        __syncthreads();
        compute_chunk(Ss, Ws, ty, tx, acc);
        __syncthreads();
    }

    const int b0 = ty * 8;
    const int hbase = htile * 128 + tx;
    float bias[8];
#pragma unroll
    for (int j = 0; j < 8; j++) {
        const int h = hbase + 16 * j;
        bias[j] = b_ih[h] + b_hh[h];
    }
#pragma unroll
    for (int i = 0; i < 8; i++) {
        const size_t row = ((size_t)mtile * 128 + b0 + i) * N_HID;
#pragma unroll
        for (int j = 0; j < 8; j++) {
            g_xp[row + hbase + 16 * j] = lo32(acc[i][j]) + hi32(acc[i][j]) + bias[j];
        }
    }
}

// Persistent recurrence + readout. 128 CTAs, all co-resident; 2 grid barriers/step.
__global__ __launch_bounds__(256, 1) void rnn_persistent(const float* __restrict__ W_hh,
                                                         const float* __restrict__ W_ro,
                                                         const float* __restrict__ b_ro,
                                                         float* __restrict__ out) {
    __shared__ alignas(16) float2 Ss[KPAIRS][128];
    __shared__ alignas(16) float2 Ws[KPAIRS][128];
    const int tid = threadIdx.x;
    const int tx = tid & 15, ty = tid >> 4;
    const int htile = blockIdx.x >> 4;     // 0..7
    const int ks = blockIdx.x & 15;        // 0..15
    const int b0 = ty * 8;
    const int gidx = blockIdx.x * 256 + tid;   // global float4 index for reduce phase
    unsigned target = 0;

    for (int t = 0; t < T_STEPS; t++) {
        // ---- phase A: partial[ks][b][h] = sum_{k in slice} state[b][k] * W_hh[h][k] ----
        unsigned long long acc[8][8];
#pragma unroll
        for (int i = 0; i < 8; i++)
#pragma unroll
            for (int j = 0; j < 8; j++) acc[i][j] = 0ull;

#pragma unroll
        for (int c = 0; c < KSLICE / KC; c++) {
            const int k0 = ks * KSLICE + c * KC;
            load_tile(Ss, g_state, 0,                   N_HID, k0, tid);
            load_tile(Ws, W_hh,    (size_t)htile * 128, N_HID, k0, tid);
            __syncthreads();
            compute_chunk(Ss, Ws, ty, tx, acc);
            __syncthreads();
        }
        {
            const int hbase = htile * 128 + tx;
            float* __restrict__ po = g_partial + (size_t)ks * BATCH * N_HID;
#pragma unroll
            for (int i = 0; i < 8; i++) {
                const size_t row = (size_t)(b0 + i) * N_HID;
#pragma unroll
                for (int j = 0; j < 8; j++) {
                    po[row + hbase + 16 * j] = lo32(acc[i][j]) + hi32(acc[i][j]);
                }
            }
        }
        grid_barrier(++target);

        // ---- phase B: state = tanh(xp[t] + sum_ks partial[ks]) (fixed-order sum) ----
        {
            float4 s = reinterpret_cast<const float4*>(
                g_xp + (size_t)t * BATCH * N_HID)[gidx];
#pragma unroll
            for (int k2 = 0; k2 < SPLITK; k2++) {
                const float4 p = reinterpret_cast<const float4*>(
                    g_partial + (size_t)k2 * BATCH * N_HID)[gidx];
                s.x += p.x; s.y += p.y; s.z += p.z; s.w += p.w;
            }
            reinterpret_cast<float4*>(g_state)[gidx] =
                make_float4(tanhf(s.x), tanhf(s.y), tanhf(s.z), tanhf(s.w));
        }
        grid_barrier(++target);
    }

    // ---- readout: out = state @ W_ro^T + b_ro (split-K over 16 CTAs) ----
    if (blockIdx.x < SPLITK) {
        unsigned long long acc[8][8];
#pragma unroll
        for (int i = 0; i < 8; i++)
#pragma unroll
            for (int j = 0; j < 8; j++) acc[i][j] = 0ull;

#pragma unroll
        for (int c = 0; c < KSLICE / KC; c++) {
            const int k0 = blockIdx.x * KSLICE + c * KC;
            load_tile(Ss, g_state, 0, N_HID, k0, tid);
            load_tile(Ws, W_ro,    0, N_HID, k0, tid);
            __syncthreads();
            compute_chunk(Ss, Ws, ty, tx, acc);
            __syncthreads();
        }
        float* __restrict__ po = g_partial + (size_t)blockIdx.x * BATCH * N_OUT;
#pragma unroll
        for (int i = 0; i < 8; i++) {
            const size_t row = (size_t)(b0 + i) * N_OUT;
#pragma unroll
            for (int j = 0; j < 8; j++) {
                po[row + tx + 16 * j] = lo32(acc[i][j]) + hi32(acc[i][j]);
            }
        }
    }
    grid_barrier(++target);

    if (blockIdx.x < 16) {
        const int idx = blockIdx.x * 256 + tid;   // [0, 4096) float4 of the 128x128 output
        float4 s = make_float4(0.f, 0.f, 0.f, 0.f);
#pragma unroll
        for (int k2 = 0; k2 < SPLITK; k2++) {
            const float4 p = reinterpret_cast<const float4*>(
                g_partial + (size_t)k2 * BATCH * N_OUT)[idx];
            s.x += p.x; s.y += p.y; s.z += p.z; s.w += p.w;
        }
        const int o0 = (idx * 4) & (N_OUT - 1);
        const float4 bb = *reinterpret_cast<const float4*>(b_ro + o0);
        s.x += bb.x; s.y += bb.y; s.z += bb.z; s.w += bb.w;
        reinterpret_cast<float4*>(out)[idx] = s;
    }
}

// -------- launch (3 graph nodes total) --------
extern "C" void kernel_launch(void* const* d_in, const int* in_sizes, int n_in,
                              void* d_out, int out_size) {
    const float* x    = (const float*)d_in[0];   // [512,128,256]
    const float* W_ih = (const float*)d_in[1];   // [1024,256]
    const float* W_hh = (const float*)d_in[2];   // [1024,1024]
    const float* b_ih = (const float*)d_in[3];   // [1024]
    const float* b_hh = (const float*)d_in[4];   // [1024]
    const float* W_ro = (const float*)d_in[5];   // [128,1024]
    const float* b_ro = (const float*)d_in[6];   // [128]
    float* out = (float*)d_out;                  // [128,128]

    (void)in_sizes; (void)n_in; (void)out_size;

    init_kernel<<<128, 256>>>();
    xproj_kernel<<<dim3(T_STEPS * BATCH / 128, N_HID / 128), 256>>>(x, W_ih, b_ih, b_hh);
    rnn_persistent<<<NCTA, 256>>>(W_hh, W_ro, b_ro, out);
}